// round 16
// baseline (speedup 1.0000x reference)
#include <cuda_runtime.h>
#include <math.h>

// StatefulSynapseNet, R16: phase-1 flipped to lane=o (all 32 lanes useful ->
// 784 FFMA2/pair vs 896) with x rows as uniform-broadcast LDG.128 and W1
// lane-distinct from shared. H stays in registers: scan reads accumulators
// directly (transpose eliminated); spikes exit as ballot masks kept in
// per-lane registers; phase 2 (lane=t, const-port W2, o-halves) reconstructs
// binary spikes via ALU bit tricks. Deferred synapse filter (R13) retained.

typedef unsigned long long ull;

__device__ __forceinline__ ull pack2(float lo, float hi) {
    ull r; asm("mov.b64 %0, {%1,%2};" : "=l"(r) : "f"(lo), "f"(hi)); return r;
}
__device__ __forceinline__ void unpack2(ull v, float& lo, float& hi) {
    asm("mov.b64 {%0,%1}, %2;" : "=f"(lo), "=f"(hi) : "l"(v));
}
__device__ __forceinline__ ull ffma2(ull a, ull b, ull c) {
    ull d; asm("fma.rn.f32x2 %0, %1, %2, %3;" : "=l"(d) : "l"(a), "l"(b), "l"(c)); return d;
}
__device__ __forceinline__ float set_ge(float a, float b) {
    float d; asm("set.ge.f32.f32 %0, %1, %2;" : "=f"(d) : "f"(a), "f"(b)); return d;
}
// spike bit o of mask m -> 1.0f or 0.0f (shift/shift/and, alu pipe)
__device__ __forceinline__ float bitf(unsigned m, int o) {
    return __uint_as_float((unsigned)(((int)(m << (31 - o))) >> 31) & 0x3F800000u);
}

#define T_DIM 28
#define F_DIM 28
#define C1 32
#define C2 10
#define WARPS 4
#define SPW 2
#define H2P 29
#define ZREG (2 * C2 * H2P)   // z region per warp: A then B, 580 floats

// constant/stage layout (floats) — same as R13/R15
#define OFF_W1T 0          // [f*32 + o] = W1[o*28+f]
#define OFF_W2  896        // [j*32 + o]
#define OFF_B1  1216
#define OFF_B2  1248
#define OFF_ITAU 1258
#define CP_SIZE 1280

__constant__ __align__(16) float c_P[CP_SIZE];
__device__   __align__(16) float g_stage[CP_SIZE];

__global__ void setup_kernel(const float* __restrict__ W1,
                             const float* __restrict__ b1,
                             const float* __restrict__ w_syn,
                             const float* __restrict__ W2,
                             const float* __restrict__ b2)
{
    int i = threadIdx.x;
    for (int idx = i; idx < C1 * F_DIM; idx += 1024) {
        int f = idx >> 5, o = idx & 31;
        g_stage[OFF_W1T + idx] = W1[o * F_DIM + f];
    }
    for (int idx = i; idx < C2 * C1; idx += 1024)
        g_stage[OFF_W2 + idx] = W2[idx];
    if (i < C1) g_stage[OFF_B1 + i] = b1[i];
    if (i < C2) g_stage[OFF_B2 + i] = b2[i];
    if (i == 0) g_stage[OFF_ITAU] = 1.0f / (1.0f + expf(-w_syn[0]));
}

__global__ __launch_bounds__(WARPS * 32, 7)
void snn_kernel(const float* __restrict__ x, float* __restrict__ out, int N)
{
    __shared__ float sh_w1[F_DIM * C1];            // [f*32 + o]: bank = o, cf
    __shared__ float sh_z[WARPS * ZREG];

    const int tid  = threadIdx.x;
    const int lane = tid & 31;
    const int warp = tid >> 5;

    // stage W1 once per block (coalesced)
    for (int i = tid; i < F_DIM * C1; i += WARPS * 32)
        sh_w1[i] = g_stage[OFF_W1T + i];
    __syncthreads();

    const int n0 = (blockIdx.x * WARPS + warp) * SPW;
    if (n0 >= N) return;
    const bool has_b = (n0 + 1 < N);
    const int n1 = has_b ? (n0 + 1) : n0;

    float* zA = sh_z + warp * ZREG;                // z[j][t] pitch 29, sample A
    float* zB = zA + C2 * H2P;                     // sample B

    // ---- phase 1: lane = o. acc[p] = (H[2p][o], H[2p+1][o]) ----
    ull accA[T_DIM / 2], accB[T_DIM / 2];
    {
        const float b1o = __ldg(&g_stage[OFF_B1 + lane]);
        const ull binit = pack2(b1o, b1o);
#pragma unroll
        for (int p = 0; p < T_DIM / 2; ++p) { accA[p] = binit; accB[p] = binit; }
    }

    const ulonglong2* xA = reinterpret_cast<const ulonglong2*>(x + (size_t)n0 * (F_DIM * T_DIM));
    const ulonglong2* xB = reinterpret_cast<const ulonglong2*>(x + (size_t)n1 * (F_DIM * T_DIM));

#pragma unroll 2
    for (int f = 0; f < F_DIM; ++f) {
        float wf = sh_w1[f * C1 + lane];           // lane-distinct, conflict-free
        ull  wp = pack2(wf, wf);
        const ulonglong2* ra = xA + f * 7;         // 7 x 16B per row, aligned
        const ulonglong2* rb = xB + f * 7;
#pragma unroll
        for (int q = 0; q < 7; ++q) {
            ulonglong2 av = __ldg(ra + q);         // uniform broadcast, 1 wavefront
            ulonglong2 bv = __ldg(rb + q);
            accA[2 * q]     = ffma2(av.x, wp, accA[2 * q]);
            accA[2 * q + 1] = ffma2(av.y, wp, accA[2 * q + 1]);
            accB[2 * q]     = ffma2(bv.x, wp, accB[2 * q]);
            accB[2 * q + 1] = ffma2(bv.y, wp, accB[2 * q + 1]);
        }
    }

    // ---- IF scan (lane = o): accs read from registers; masks kept per-lane ----
    unsigned mA = 0, mB = 0;
    {
        float va = 0.0f, vb = 0.0f;
#pragma unroll
        for (int t = 0; t < T_DIM; ++t) {
            float lo, hi, ha, hb;
            unpack2(accA[t >> 1], lo, hi);  ha = (t & 1) ? hi : lo;
            unpack2(accB[t >> 1], lo, hi);  hb = (t & 1) ? hi : lo;
            va += ha;                           vb += hb;
            bool pa = (va >= 1.0f);             bool pb = (vb >= 1.0f);
            unsigned ba = __ballot_sync(0xffffffffu, pa);
            unsigned bb = __ballot_sync(0xffffffffu, pb);
            va = pa ? 0.0f : va;                vb = pb ? 0.0f : vb;   // hard reset
            if (lane == t) { mA = ba; mB = bb; }   // row-mask lands in lane t
        }
    }
    // ballot is warp-synchronous; handoff is in registers — no syncwarp needed

    // ---- phase 2: lane = t; binary spikes from mask, W2 via const port ----
    const bool tl = (lane < T_DIM);
    {
        float pA[C2], pB[C2];
#pragma unroll
        for (int j = 0; j < C2; ++j) { pA[j] = 0.0f; pB[j] = 0.0f; }

        if (tl) {
#pragma unroll
            for (int half = 0; half < 2; ++half) {
                ull sqa[8], sqb[8];
#pragma unroll
                for (int q = 0; q < 8; ++q) {          // ALU reconstruct (idle pipe)
                    int o0 = half * 16 + 2 * q;
                    sqa[q] = pack2(bitf(mA, o0), bitf(mA, o0 + 1));
                    sqb[q] = pack2(bitf(mB, o0), bitf(mB, o0 + 1));
                }
#pragma unroll
                for (int j = 0; j < C2; ++j) {
                    ull a2 = 0ULL, b2a = 0ULL;
                    const ulonglong2* wq2 =
                        reinterpret_cast<const ulonglong2*>(c_P + OFF_W2 + j * C1 + half * 16);
#pragma unroll
                    for (int q = 0; q < 4; ++q) {
                        ulonglong2 w = wq2[q];
                        a2  = ffma2(sqa[2 * q],     w.x, a2);
                        b2a = ffma2(sqb[2 * q],     w.x, b2a);
                        a2  = ffma2(sqa[2 * q + 1], w.y, a2);
                        b2a = ffma2(sqb[2 * q + 1], w.y, b2a);
                    }
                    float u0, u1, v0, v1;
                    unpack2(a2, u0, u1);
                    unpack2(b2a, v0, v1);
                    pA[j] += u0 + u1;
                    pB[j] += v0 + v1;
                }
            }
#pragma unroll
            for (int j = 0; j < C2; ++j) {
                zA[j * H2P + lane] = pA[j];        // z[j][t]; b2 folded later
                zB[j * H2P + lane] = pB[j];
            }
        }
    }
    __syncwarp();

    // ---- final scan (20 lanes): synapse filter u + IF scan + mean ----
    {
        int sj = lane & 15;
        int ss = lane >> 4;
        if (sj < C2 && (ss == 0 || has_b)) {
            const float* z = ss ? zB : zA;
            const float itau = c_P[OFF_ITAU];
            const float bj = c_P[OFF_B2 + sj];
            float u = 0.0f, v = 0.0f, cnt = 0.0f;
#pragma unroll
            for (int t = 0; t < T_DIM; ++t) {
                u = fmaf(u, -itau, u) + z[sj * H2P + t];   // u = u - u*itau + z
                v += u + bj;                               // h2 = u + b2
                float s = set_ge(v, 1.0f);
                cnt += s;
                v = fmaf(v, -s, v);                        // exact reset
            }
            int nn = ss ? n1 : n0;
            out[(size_t)nn * C2 + sj] = cnt * (1.0f / 28.0f);
        }
    }
}

extern "C" void kernel_launch(void* const* d_in, const int* in_sizes, int n_in,
                              void* d_out, int out_size)
{
    const float* x     = (const float*)d_in[0];
    const float* W1    = (const float*)d_in[1];
    const float* b1    = (const float*)d_in[2];
    const float* w_syn = (const float*)d_in[3];
    const float* W2    = (const float*)d_in[4];
    const float* b2    = (const float*)d_in[5];
    float* out = (float*)d_out;

    const int N = in_sizes[0] / (F_DIM * T_DIM);

    setup_kernel<<<1, 1024>>>(W1, b1, w_syn, W2, b2);

    void* sp = nullptr;
    cudaGetSymbolAddress(&sp, g_stage);
    cudaMemcpyToSymbolAsync(c_P, sp, CP_SIZE * sizeof(float), 0,
                            cudaMemcpyDeviceToDevice, 0);

    const int spb = WARPS * SPW;
    const int blocks = (N + spb - 1) / spb;
    snn_kernel<<<blocks, WARPS * 32>>>(x, out, N);
}